// round 11
// baseline (speedup 1.0000x reference)
#include <cuda_runtime.h>
#include <math.h>

// Problem constants
#define NIMG 8
#define HWA  40000      // 200*200
#define NCLS 80
#define NB   4096       // histogram buckets (256 per octave of D)
#define CAPC 4096       // candidate buffer capacity (per image)
#define TOPK 1000
#define OUTK 100
#define REQ  200        // required sampled (1/8) suffix count -> true ~1600

#define THRX (-2.9444389791664403f)   // logit(0.05)

typedef unsigned long long ULL;

// ---------------- device scratch (no allocs allowed) ----------------
// Invariant: g_hist and g_cnt are ZERO at the start of every kernel_launch
// sequence. CUDA zero-inits __device__ globals; k_thresh re-zeroes g_hist
// after consuming it and k_final re-zeroes g_cnt after reading it, so the
// invariant is self-maintaining across graph replays (deterministic).
__device__ unsigned int g_hist[NIMG * NB];
__device__ unsigned int g_cnt[NIMG];
__device__ unsigned int g_thr[NIMG];
__device__ ULL          g_cand[NIMG * CAPC];
__device__ __align__(16) float g_xmin[NIMG * HWA];   // per-loc x threshold

// ---------------- FMA-only exp (no MUFU), monotone to ~1e-7 ----------------
__device__ __forceinline__ float exp_fma(float t) {
    float y = t * 1.4426950408889634f;
    float z = y + 12582912.0f;
    float n = z - 12582912.0f;
    float g = y - n;
    float p = 1.5403530393e-4f;
    p = fmaf(p, g, 1.3333558146e-3f);
    p = fmaf(p, g, 9.6181291071e-3f);
    p = fmaf(p, g, 5.5504108664e-2f);
    p = fmaf(p, g, 2.4022650696e-1f);
    p = fmaf(p, g, 6.9314718056e-1f);
    p = fmaf(p, g, 1.0f);
    int ni = (int)n;
    return p * __int_as_float((ni + 127) << 23);
}

// ---------------- FMA-only natural log, |err| < ~3e-6 ----------------------
__device__ __forceinline__ float log_poly(float v) {
    unsigned u = __float_as_uint(v);
    int e = (int)(u >> 23) - 127;
    float m = __uint_as_float((u & 0x7FFFFFu) | 0x3F800000u);  // [1,2)
    if (m >= 1.41421356f) { m *= 0.5f; e += 1; }               // [0.707,1.414)
    float t = m - 1.0f;                                         // [-0.293,0.414]
    float p = 0.0909090909f;                 // 1/11
    p = fmaf(p, t, -0.1f);
    p = fmaf(p, t,  0.1111111111f);
    p = fmaf(p, t, -0.125f);
    p = fmaf(p, t,  0.1428571429f);
    p = fmaf(p, t, -0.1666666667f);
    p = fmaf(p, t,  0.2f);
    p = fmaf(p, t, -0.25f);
    p = fmaf(p, t,  0.3333333333f);
    p = fmaf(p, t, -0.5f);
    p = fmaf(p, t,  1.0f);
    p = p * t;
    return fmaf((float)e, 0.69314718055994531f, p);
}

// bucket from D = (1+e^-x)(1+e^-c); smaller D => higher score => higher bucket
__device__ __forceinline__ int bucket_of_D(float D) {
    int t = (int)(__float_as_uint(D) >> 15) - 32512;   // bits(1.0f)>>15
    t = t < 0 ? 0 : (t > (NB - 1) ? (NB - 1) : t);
    return (NB - 1) - t;
}

// ---------------- kernel 1: sampled surrogate histogram (1/8 of locs) -------
// grid (40, NIMG), 256 threads; shared-memory histogram per block.
__global__ void k_hist(const float* __restrict__ cls, const float* __restrict__ cent) {
    __shared__ unsigned sh[NB];
    const int n = blockIdx.y;
    for (int i = threadIdx.x; i < NB; i += 256) sh[i] = 0u;
    __syncthreads();

    const float4* c4  = (const float4*)cls;
    const float4* ct4 = (const float4*)cent;
    const int total = NCLS * 1250;           // eighth of each plane, float4s
    for (int s = blockIdx.x * 256 + threadIdx.x; s < total; s += 40 * 256) {
        int p = s / 1250;
        int r = s - p * 1250;
        float4 v  = __ldg(&c4[((size_t)(n * NCLS + p)) * 10000 + r]);
        float4 cv = __ldg(&ct4[n * 10000 + r]);
        float xs[4] = {v.x, v.y, v.z, v.w};
        float cc[4] = {cv.x, cv.y, cv.z, cv.w};
        #pragma unroll
        for (int k = 0; k < 4; k++) {
            float x = xs[k];
            if (x > THRX) {
                float cf = 1.0f + exp_fma(-cc[k]);
                float D = (1.0f + exp_fma(-x)) * cf;
                atomicAdd(&sh[bucket_of_D(D)], 1u);
            }
        }
    }
    __syncthreads();
    for (int i = threadIdx.x; i < NB; i += 256) {
        unsigned v = sh[i];
        if (v) atomicAdd(&g_hist[n * NB + i], v);
    }
}

// ---------------- kernel 2: threshold bucket; re-zeroes g_hist --------------
__global__ void k_thresh() {
    const int n = blockIdx.x;
    const int t = threadIdx.x;
    unsigned part = 0;
    int base = n * NB + t * 16;
    #pragma unroll
    for (int k = 0; k < 16; k++) part += g_hist[base + k];

    __shared__ unsigned S[256];
    __shared__ int Bsel;
    S[t] = part;
    if (t == 0) Bsel = 0;
    __syncthreads();
    for (int off = 1; off < 256; off <<= 1) {
        unsigned a = (t + off < 256) ? S[t + off] : 0u;
        __syncthreads();
        S[t] += a;
        __syncthreads();
    }
    unsigned nxt = (t < 255) ? S[t + 1] : 0u;
    if (S[t] >= REQ && nxt < REQ) {
        unsigned acc = nxt;
        int B = t * 16;
        for (int b = t * 16 + 15; b >= t * 16; b--) {
            acc += g_hist[n * NB + b];
            if (acc >= REQ) { B = b; break; }
        }
        B -= 2;                 // slack buckets: surrogate monotonicity error
        Bsel = B < 0 ? 0 : B;
    }
    __syncthreads();
    if (t == 0) g_thr[n] = (S[0] >= REQ) ? (unsigned)Bsel : 0u;
    // restore the all-zero invariant for the next replay
    #pragma unroll
    for (int k = 0; k < 16; k++) g_hist[base + k] = 0u;
}

// ---------------- kernel 2b: invert threshold into per-loc xmin table -------
// bucket >= thr  <=>  D < edge  <=>  x > log(cf) - log(edge - cf)
__global__ void k_xmin(const float* __restrict__ cent) {
    const int n = blockIdx.y;
    int idx = blockIdx.x * 256 + threadIdx.x;
    if (idx >= HWA) return;
    int i = n * HWA + idx;
    unsigned thr = __ldg(&g_thr[n]);
    float edge = __uint_as_float(((unsigned)(NB - thr) + 32512u) << 15);
    float cf = 1.0f + exp_fma(-__ldg(&cent[i]));
    float em = edge - cf;
    float xm;
    if (em > 1.2e-38f)
        xm = fmaxf(THRX, log_poly(cf) - log_poly(em) - 1e-2f);  // conservative
    else
        xm = 3.0e38f;                                           // nothing passes
    g_xmin[i] = xm;
}

// ---------------- kernel 3: full sweep, collect exact-score candidates ------
// grid (10, NIMG*NCLS), 256 threads; 4 front-batched float4 loads per thread.
__global__ void k_collect(const float* __restrict__ cls, const float* __restrict__ cent) {
    const int plane = blockIdx.y;
    const int n = plane / NCLS;
    const int c = plane - n * NCLS;
    const float4* c4  = (const float4*)cls;
    const float4* xm4 = (const float4*)g_xmin;
    const int t = blockIdx.x * 256 + threadIdx.x;   // 0..2559

    float4 v[4], xm[4];
    #pragma unroll
    for (int k = 0; k < 4; k++) {
        int r = t + k * 2560;
        if (r < 10000) {
            v[k]  = __ldcs(&c4[(size_t)plane * 10000 + r]);   // streaming
            xm[k] = __ldg(&xm4[n * 10000 + r]);
        } else {
            xm[k] = make_float4(3e38f, 3e38f, 3e38f, 3e38f);
            v[k]  = make_float4(0.f, 0.f, 0.f, 0.f);
        }
    }
    #pragma unroll
    for (int k = 0; k < 4; k++) {
        int r = t + k * 2560;
        float xs[4] = {v[k].x, v[k].y, v[k].z, v[k].w};
        float ms[4] = {xm[k].x, xm[k].y, xm[k].z, xm[k].w};
        #pragma unroll
        for (int q = 0; q < 4; q++) {
            float x = xs[q];
            if (x > ms[q]) {
                int loc = r * 4 + q;
                float cv  = __ldg(&cent[n * HWA + loc]);
                float scv = 1.0f / (1.0f + expf(-cv));    // exact sigmoid (cent)
                float sx  = 1.0f / (1.0f + expf(-x));     // exact sigmoid (cls)
                float sv  = sx * scv;                     // exact score
                unsigned fidx = (unsigned)loc * NCLS + (unsigned)c;
                ULL key = ((ULL)__float_as_uint(sv) << 32) | (unsigned)(~fidx);
                unsigned pos = atomicAdd(&g_cnt[n], 1u);
                if (pos < CAPC) g_cand[(size_t)n * CAPC + pos] = key;
            }
        }
    }
}

// ---------------- kernel 4: sort + decode + per-label NMS + output ----------
// dyn smem: sortb 32KB | 10 float[1024] | slab u32[1024] | sList u16[1024] | 3x u8[1024]
#define SMEMB (32768 + 10 * 4096 + 4096 + 2048 + 3 * 1024)

__device__ __forceinline__ ULL shfl_xor_ull(ULL v, int j) {
    return __shfl_xor_sync(0xffffffffu, v, j);
}

__global__ void __launch_bounds__(1024, 1)
k_final(const float* __restrict__ breg, const float* __restrict__ loc2,
        const int* __restrict__ sizes, float* __restrict__ out) {
    extern __shared__ char sm[];
    ULL* sortb = (ULL*)sm;                                     // [0, 32KB)
    float* ox1 = (float*)(sm + 32768);
    float* oy1 = ox1 + 1024;
    float* ox2 = oy1 + 1024;
    float* oy2 = ox2 + 1024;
    float* oar = oy2 + 1024;
    float* ux1 = oar + 1024;
    float* uy1 = ux1 + 1024;
    float* ux2 = uy1 + 1024;
    float* uy2 = ux2 + 1024;
    float* ssc = uy2 + 1024;
    unsigned* slab        = (unsigned*)(ssc + 1024);
    unsigned short* sList = (unsigned short*)(slab + 1024);
    unsigned char* vflag  = (unsigned char*)(sList + 1024);
    unsigned char* keep   = vflag + 1024;
    unsigned char* rem    = keep + 1024;
    __shared__ int labCnt[NCLS];
    __shared__ int labOff[NCLS + 1];
    __shared__ unsigned wpre[32];

    const int n   = blockIdx.x;
    const int tid = threadIdx.x;
    const int wid = tid >> 5, lane = tid & 31;

    unsigned M = g_cnt[n];
    if (M > CAPC) M = CAPC;
    unsigned Msort = (M <= 2048u) ? 2048u : 4096u;
    for (unsigned i = tid; i < Msort; i += 1024)
        sortb[i] = (i < M) ? g_cand[(size_t)n * CAPC + i] : 0ULL;
    keep[tid] = 0; rem[tid] = 0;
    if (tid < NCLS) labCnt[tid] = 0;
    __syncthreads();

    // ---- bitonic sort, descending (score desc, then orig idx asc via ~idx) ----
    if (Msort == 2048u) {
        // hybrid: j<=32 steps register-resident per 64-element warp chunk
        const int ia = wid * 64 + lane;
        const int ib = ia + 32;
        ULL a = sortb[ia], b = sortb[ib];
        #pragma unroll
        for (unsigned k2 = 2; k2 <= 64; k2 <<= 1) {
            #pragma unroll
            for (unsigned j = k2 >> 1; j >= 1; j >>= 1) {
                if (j == 32) {
                    bool desc = ((ia & k2) == 0);
                    if (desc ? (a < b) : (a > b)) { ULL t = a; a = b; b = t; }
                } else {
                    ULL pa = shfl_xor_ull(a, j);
                    ULL pb = shfl_xor_ull(b, j);
                    bool ta = (((ia & j) == 0) == ((ia & k2) == 0));
                    bool tb = (((ib & j) == 0) == ((ib & k2) == 0));
                    a = ta ? (a > pa ? a : pa) : (a < pa ? a : pa);
                    b = tb ? (b > pb ? b : pb) : (b < pb ? b : pb);
                }
            }
        }
        sortb[ia] = a; sortb[ib] = b;
        __syncthreads();
        for (unsigned k2 = 128; k2 <= 2048; k2 <<= 1) {
            for (unsigned j = k2 >> 1; j >= 64; j >>= 1) {
                #pragma unroll
                for (unsigned h = 0; h < 2; h++) {
                    unsigned i = tid + h * 1024;
                    unsigned ixj = i ^ j;
                    if (ixj > i) {
                        ULL x = sortb[i], y = sortb[ixj];
                        bool desc = ((i & k2) == 0);
                        if (desc ? (x < y) : (x > y)) { sortb[i] = y; sortb[ixj] = x; }
                    }
                }
                __syncthreads();
            }
            a = sortb[ia]; b = sortb[ib];
            {
                bool desc = ((ia & k2) == 0);
                if (desc ? (a < b) : (a > b)) { ULL t = a; a = b; b = t; }
            }
            #pragma unroll
            for (unsigned j = 16; j >= 1; j >>= 1) {
                ULL pa = shfl_xor_ull(a, j);
                ULL pb = shfl_xor_ull(b, j);
                bool ta = (((ia & j) == 0) == ((ia & k2) == 0));
                bool tb = (((ib & j) == 0) == ((ib & k2) == 0));
                a = ta ? (a > pa ? a : pa) : (a < pa ? a : pa);
                b = tb ? (b > pb ? b : pb) : (b < pb ? b : pb);
            }
            sortb[ia] = a; sortb[ib] = b;
            __syncthreads();
        }
    } else {
        // fallback (M > 2048, not expected): plain smem bitonic over 4096
        for (unsigned k2 = 2; k2 <= Msort; k2 <<= 1) {
            for (unsigned j = k2 >> 1; j > 0; j >>= 1) {
                for (unsigned i = tid; i < Msort; i += 1024) {
                    unsigned ixj = i ^ j;
                    if (ixj > i) {
                        ULL x = sortb[i], y = sortb[ixj];
                        bool desc = ((i & k2) == 0);
                        if (desc ? (x < y) : (x > y)) { sortb[i] = y; sortb[ixj] = x; }
                    }
                }
                __syncthreads();
            }
        }
    }

    // ---- decode entry `tid` (only first 1024 matter; TOPK=1000) ----
    {
        ULL key = sortb[tid];
        float s = __uint_as_float((unsigned)(key >> 32));
        unsigned idx = ~(unsigned)key;
        bool v = (tid < TOPK) && (s > 0.0f);
        float X1=0,Y1=0,X2=0,Y2=0, O1=0,O2=0,O3=0,O4=0, AR=1.0f;
        unsigned lab = 0;
        if (v) {
            unsigned loc = idx / (unsigned)NCLS;
            unsigned cc  = idx - loc * (unsigned)NCLS;
            unsigned lb  = cc + 1u;
            float lx = loc2[2 * loc], ly = loc2[2 * loc + 1];
            float r0 = breg[((size_t)n * 4 + 0) * HWA + loc];
            float r1 = breg[((size_t)n * 4 + 1) * HWA + loc];
            float r2 = breg[((size_t)n * 4 + 2) * HWA + loc];
            float r3 = breg[((size_t)n * 4 + 3) * HWA + loc];
            float himg = (float)sizes[n * 2 + 0];
            float wimg = (float)sizes[n * 2 + 1];
            float x1 = lx - r0, y1 = ly - r1, x2 = lx + r2, y2 = ly + r3;
            x1 = fminf(fmaxf(x1, 0.0f), wimg - 1.0f);
            y1 = fminf(fmaxf(y1, 0.0f), himg - 1.0f);
            x2 = fminf(fmaxf(x2, 0.0f), wimg - 1.0f);
            y2 = fminf(fmaxf(y2, 0.0f), himg - 1.0f);
            float bw = x2 - x1 + 1.0f, bh = y2 - y1 + 1.0f;
            v = (bw >= 0.0f) && (bh >= 0.0f);
            if (v) {
                lab = lb;
                float off = __fmul_rn((float)lb, 100000.0f);
                X1 = x1; Y1 = y1; X2 = x2; Y2 = y2;
                O1 = __fadd_rn(x1, off); O2 = __fadd_rn(y1, off);
                O3 = __fadd_rn(x2, off); O4 = __fadd_rn(y2, off);
                AR = __fmul_rn(__fadd_rn(__fsub_rn(O3, O1), 1.0f),
                               __fadd_rn(__fsub_rn(O4, O2), 1.0f));
                atomicAdd(&labCnt[lb - 1], 1);
            }
        }
        ux1[tid]=X1; uy1[tid]=Y1; ux2[tid]=X2; uy2[tid]=Y2;
        ox1[tid]=O1; oy1[tid]=O2; ox2[tid]=O3; oy2[tid]=O4;
        oar[tid]=AR; ssc[tid]=s;  slab[tid]=lab; vflag[tid] = v ? 1 : 0;
    }
    __syncthreads();
    if (tid == 0) {
        labOff[0] = 0;
        for (int w = 0; w < NCLS; w++) labOff[w + 1] = labOff[w] + labCnt[w];
    }
    __syncthreads();

    // per-label gather (ordered) + greedy NMS; one warp per label.
    // Cross-label IoU is exactly 0 (class offset), so greedy decomposes.
    for (int L = wid; L < NCLS; L += 32) {
        int base = labOff[L];
        int cnt = 0;
        for (int s0 = 0; s0 < 1024; s0 += 32) {
            int i = s0 + lane;
            bool m = vflag[i] && (slab[i] == (unsigned)(L + 1));
            unsigned bal = __ballot_sync(0xffffffffu, m);
            if (m) sList[base + cnt + __popc(bal & ((1u << lane) - 1u))] =
                       (unsigned short)i;
            cnt += __popc(bal);
        }
        __syncwarp();
        for (int a = 0; a < cnt; a++) {
            int ia2 = sList[base + a];
            unsigned char rr = rem[base + a];       // warp-uniform
            if (!rr) {
                if (lane == 0) keep[ia2] = 1;
                float a1 = ox1[ia2], b1 = oy1[ia2], a2 = ox2[ia2], b2 = oy2[ia2];
                float ar = oar[ia2];
                for (int b = a + 1 + lane; b < cnt; b += 32) {
                    int jb = sList[base + b];
                    float iw_ = fmaxf(__fadd_rn(__fsub_rn(fminf(a2, ox2[jb]),
                                                          fmaxf(a1, ox1[jb])), 1.0f), 0.0f);
                    float ih_ = fmaxf(__fadd_rn(__fsub_rn(fminf(b2, oy2[jb]),
                                                          fmaxf(b1, oy1[jb])), 1.0f), 0.0f);
                    float inter = __fmul_rn(iw_, ih_);
                    float den   = __fsub_rn(__fadd_rn(ar, oar[jb]), inter);
                    float iou   = __fdiv_rn(inter, den);
                    if (iou > 0.6f) rem[base + b] = 1;
                }
            }
            __syncwarp();
        }
    }
    __syncthreads();

    // zero output, then emit first 100 kept (already score-descending)
    if (tid < OUTK * 6) out[(size_t)n * OUTK * 6 + tid] = 0.0f;
    bool kp = keep[tid] != 0;
    unsigned bal = __ballot_sync(0xffffffffu, kp);
    if (lane == 0) wpre[wid] = __popc(bal);
    __syncthreads();
    if (tid < 32) {
        unsigned v = wpre[tid], ssum = v;
        for (int off = 1; off < 32; off <<= 1) {
            unsigned t2 = __shfl_up_sync(0xffffffffu, ssum, off);
            if ((int)tid >= off) ssum += t2;
        }
        wpre[tid] = ssum - v;   // exclusive
    }
    __syncthreads();
    if (kp) {
        unsigned rank = wpre[wid] + __popc(bal & ((1u << lane) - 1u));
        if (rank < OUTK) {
            float* o = out + (size_t)n * OUTK * 6 + (size_t)rank * 6;
            o[0] = ux1[tid]; o[1] = uy1[tid]; o[2] = ux2[tid]; o[3] = uy2[tid];
            o[4] = sqrtf(ssc[tid]);
            o[5] = (float)slab[tid];
        }
    }
    // restore the all-zero invariant for the next replay
    if (tid == 0) g_cnt[n] = 0u;
}

// ---------------- host launcher ----------------
extern "C" void kernel_launch(void* const* d_in, const int* in_sizes, int n_in,
                              void* d_out, int out_size) {
    const float* loc2 = (const float*)d_in[0];   // locations (HW,2)
    const float* cls  = (const float*)d_in[1];   // box_cls (N,C,H,W)
    const float* breg = (const float*)d_in[2];   // box_regression (N,4,H,W)
    const float* cent = (const float*)d_in[3];   // centerness (N,1,H,W)
    const int*   szs  = (const int*)d_in[4];     // image_sizes (N,2)
    float* out = (float*)d_out;                  // (N,100,6)

    cudaFuncSetAttribute(k_final, cudaFuncAttributeMaxDynamicSharedMemorySize, SMEMB);

    k_hist<<<dim3(40, NIMG), 256>>>(cls, cent);
    k_thresh<<<NIMG, 256>>>();
    k_xmin<<<dim3((HWA + 255) / 256, NIMG), 256>>>(cent);
    k_collect<<<dim3(10, NIMG * NCLS), 256>>>(cls, cent);
    k_final<<<NIMG, 1024, SMEMB>>>(breg, loc2, szs, out);
}